// round 8
// baseline (speedup 1.0000x reference)
#include <cuda_runtime.h>

// RoiPooling: fmap [1,128,128,256] f32 NHWC, roi_edges [R,4] f32
// out [R,7,7,256] f32. Adaptive max pool, reference _bin_size semantics.
//
// One output bin per thread: block (64 channel-groups x 7 bins), grid (R, 7).
// Each thread keeps a single float4 accumulator -> minimal register state ->
// high occupancy (42 warps/SM) AND full load batching (2*MW loads in flight
// via unroll-2 on y). Warp j is uniform (warp = 32 channel lanes of one bin):
// no divergence, 512B coalesced loads, loads disjoint across bins (no extra
// L2 traffic). mw specialized to 5 compact variants (I$-safe).

#define H_DIM 128
#define W_DIM 128
#define C_VEC 64          // 256 channels / 4 (float4)
#define OUT_H 7
#define OUT_W 7
#define ROW_STRIDE ((size_t)W_DIM * C_VEC)   // float4 elems per fmap row

__device__ __forceinline__ int bin_size(int L) {
    int xup = (L + OUT_H - 1) / OUT_H;            // ceil(L/7)
    int m = (xup * (OUT_H - 1) >= L) ? (xup - 1) : xup;
    return m > 1 ? m : 1;
}

__device__ __forceinline__ void fold(float4& a, const float4 v) {
    a.x = fmaxf(a.x, v.x);
    a.y = fmaxf(a.y, v.y);
    a.z = fmaxf(a.z, v.z);
    a.w = fmaxf(a.w, v.w);
}

// One thread = one (bin j, channel-group) cell. fp points at this thread's
// bin start (row y0, col l + j*mw, channel tid). Bins 0..5: compile-time
// width MW. Bin 6: dynamic width wl in [1,6], predicated loads.
template<int MW>
__device__ __forceinline__ float4 scan_bin(const float4* __restrict__ fp,
                                           int cnt, int wl, bool tail)
{
    const float NEG = __int_as_float(0xff800000);   // -inf
    float4 acc = make_float4(NEG, NEG, NEG, NEG);

    if (!tail) {
#pragma unroll 2
        for (int y = 0; y < cnt; ++y) {
            const float4* row = fp;
            fp += ROW_STRIDE;
#pragma unroll
            for (int k = 0; k < MW; ++k)
                fold(acc, __ldg(row + k * C_VEC));
        }
    } else {
#pragma unroll 2
        for (int y = 0; y < cnt; ++y) {
            const float4* row = fp;
            fp += ROW_STRIDE;
#pragma unroll
            for (int k = 0; k < 6; ++k) {
                if (k < wl)
                    fold(acc, __ldg(row + k * C_VEC));
            }
        }
    }
    return acc;
}

__global__ __launch_bounds__(448, 3)
void roi_pool_kernel(const float4* __restrict__ fmap,   // [128,128,64] float4
                     const float4* __restrict__ rois,   // [R] (l,r,t,b)
                     float4* __restrict__ out)          // [R,7,7,64] float4
{
    const int r   = blockIdx.x;       // ROI index
    const int i   = blockIdx.y;       // output row 0..6
    const int tid = threadIdx.x;      // 0..63 channel-group
    const int j   = threadIdx.y;      // 0..6 output column (warp-uniform)

    const float4 e = rois[r];
    const int l  = __float2int_rn(128.0f * e.x);
    const int rr = __float2int_rn(128.0f * e.y);
    const int t  = __float2int_rn(128.0f * e.z);
    const int b  = __float2int_rn(128.0f * e.w);

    int Lh = b - t; Lh = Lh < OUT_H ? OUT_H : (Lh > 32 ? 32 : Lh);
    int Lw = rr - l; Lw = Lw < OUT_W ? OUT_W : (Lw > 32 ? 32 : Lw);

    const int mh = bin_size(Lh);
    const int mw = bin_size(Lw);
    const int wl = Lw - (OUT_W - 1) * mw;          // last-bin width, 1..6

    const int y0 = i * mh;
    int y1 = (i == OUT_H - 1) ? Lh : (i + 1) * mh;
    if (y1 > Lh) y1 = Lh;
    const int cnt = y1 - y0;                       // 1..6

    const bool tail = (j == OUT_W - 1);            // warp-uniform branch

    const float4* fp = fmap
        + ((size_t)(t + y0) * W_DIM + (l + j * mw)) * C_VEC + tid;

    float4 acc;
    switch (mw) {
        case 1:  acc = scan_bin<1>(fp, cnt, wl, tail); break;
        case 2:  acc = scan_bin<2>(fp, cnt, wl, tail); break;
        case 3:  acc = scan_bin<3>(fp, cnt, wl, tail); break;
        case 4:  acc = scan_bin<4>(fp, cnt, wl, tail); break;
        default: acc = scan_bin<5>(fp, cnt, wl, tail); break;
    }

    out[(((size_t)r * OUT_H + i) * OUT_W + j) * C_VEC + tid] = acc;
}

extern "C" void kernel_launch(void* const* d_in, const int* in_sizes, int n_in,
                              void* d_out, int out_size)
{
    const float4* fmap = (const float4*)d_in[0];   // [1,128,128,256] f32
    const float4* rois = (const float4*)d_in[1];   // [R,4] f32
    float4* out = (float4*)d_out;

    const int R = in_sizes[1] / 4;

    dim3 grid(R, OUT_H);
    dim3 block(C_VEC, OUT_W);
    roi_pool_kernel<<<grid, block>>>(fmap, rois, out);
}

// round 11
// speedup vs baseline: 1.2010x; 1.2010x over previous
#include <cuda_runtime.h>

// RoiPooling: fmap [1,128,128,256] f32 NHWC, roi_edges [R,4] f32
// out [R,7,7,256] f32. Adaptive max pool, reference _bin_size semantics.
//
// R5 structure (proven safe/fast): mw-specialized (5 variants, I$-safe),
// column-split across threadIdx.y (ty=0: bins [0,JS), ty=1: bins [JS,7)),
// predicated tail bin. This round: __launch_bounds__(128,6) for register
// headroom + explicit load-batch-then-fold per row so ptxas front-batches
// the LDGs (high MLP), 32-bit offset arithmetic.

#define H_DIM 128
#define W_DIM 128
#define C_VEC 64          // 256 channels / 4 (float4)
#define OUT_H 7
#define OUT_W 7
#define ROW_STRIDE (W_DIM * C_VEC)    // float4 elems per fmap row (8192)

__device__ __forceinline__ int bin_size(int L) {
    int xup = (L + OUT_H - 1) / OUT_H;            // ceil(L/7)
    int m = (xup * (OUT_H - 1) >= L) ? (xup - 1) : xup;
    return m > 1 ? m : 1;
}

__device__ __forceinline__ void fold(float4& a, const float4 v) {
    a.x = fmaxf(a.x, v.x);
    a.y = fmaxf(a.y, v.y);
    a.z = fmaxf(a.z, v.z);
    a.w = fmaxf(a.w, v.w);
}

// One half-block: ty=0 handles bins [0,JS), ty=1 handles [JS,7).
// Bins with compile-time width MW are loaded as one batched temp array
// per row (front-batched LDGs -> MLP = NL), then folded. Tail bin
// (second half only) uses predicated load+fold pairs.
template<int MW, bool FIRST>
__device__ __forceinline__ void run_half(const float4* __restrict__ fp,
                                         int cnt, int wl,
                                         float4* __restrict__ obase)
{
    // Balance expected loads: JS ~= round((6*MW + 3.5) / (2*MW))
    constexpr int JS = (14 * MW + 7) / (4 * MW);   // MW=1..5 -> 5,4,4,3,3
    constexpr int J0 = FIRST ? 0 : JS;
    constexpr int J1 = FIRST ? JS : (OUT_W - 1);   // full-width bins only
    constexpr int NB = (FIRST ? JS : OUT_W - JS);  // accs incl. tail bin
    constexpr int NL = (J1 - J0) * MW;             // batched loads per row

    const float NEG = __int_as_float(0xff800000);   // -inf
    float4 acc[NB];
#pragma unroll
    for (int j = 0; j < NB; ++j)
        acc[j] = make_float4(NEG, NEG, NEG, NEG);

    int roff = 0;                                   // 32-bit row offset
#pragma unroll 2
    for (int y = 0; y < cnt; ++y) {
        const float4* row = fp + roff;
        roff += ROW_STRIDE;

        // Batched loads for full-width bins: independent LDGs, front-batched.
        float4 v[NL];
#pragma unroll
        for (int u = 0; u < NL; ++u)
            v[u] = __ldg(row + (J0 * MW + u) * C_VEC);
#pragma unroll
        for (int u = 0; u < NL; ++u)
            fold(acc[u / MW], v[u]);

        if (!FIRST) {
            // Tail bin: dynamic width wl in [1,6], predicated.
            const float4* rowt = row + (OUT_W - 1) * MW * C_VEC;
#pragma unroll
            for (int k = 0; k < 6; ++k) {
                if (k < wl)
                    fold(acc[NB - 1], __ldg(rowt + k * C_VEC));
            }
        }
    }

#pragma unroll
    for (int j = 0; j < NB; ++j)
        obase[(J0 + j) * C_VEC] = acc[j];
}

__global__ __launch_bounds__(128, 6)
void roi_pool_kernel(const float4* __restrict__ fmap,   // [128,128,64] float4
                     const float4* __restrict__ rois,   // [R] (l,r,t,b)
                     float4* __restrict__ out)          // [R,7,7,64] float4
{
    const int r   = blockIdx.x;       // ROI index
    const int i   = blockIdx.y;       // output row 0..6
    const int tid = threadIdx.x;      // 0..63 channel-group
    const bool first = (threadIdx.y == 0);

    const float4 e = rois[r];
    const int l  = __float2int_rn(128.0f * e.x);
    const int rr = __float2int_rn(128.0f * e.y);
    const int t  = __float2int_rn(128.0f * e.z);
    const int b  = __float2int_rn(128.0f * e.w);

    int Lh = b - t; Lh = Lh < OUT_H ? OUT_H : (Lh > 32 ? 32 : Lh);
    int Lw = rr - l; Lw = Lw < OUT_W ? OUT_W : (Lw > 32 ? 32 : Lw);

    const int mh = bin_size(Lh);
    const int mw = bin_size(Lw);
    const int wl = Lw - (OUT_W - 1) * mw;          // last-bin width, 1..6

    const int y0 = i * mh;
    int y1 = (i == OUT_H - 1) ? Lh : (i + 1) * mh;
    if (y1 > Lh) y1 = Lh;
    const int cnt = y1 - y0;                       // 1..6

    const float4* fp = fmap + ((t + y0) * W_DIM + l) * C_VEC + tid;
    float4* obase = out + ((r * OUT_H + i) * OUT_W) * C_VEC + tid;

    switch (mw) {
        case 1:
            if (first) run_half<1, true >(fp, cnt, wl, obase);
            else       run_half<1, false>(fp, cnt, wl, obase);
            break;
        case 2:
            if (first) run_half<2, true >(fp, cnt, wl, obase);
            else       run_half<2, false>(fp, cnt, wl, obase);
            break;
        case 3:
            if (first) run_half<3, true >(fp, cnt, wl, obase);
            else       run_half<3, false>(fp, cnt, wl, obase);
            break;
        case 4:
            if (first) run_half<4, true >(fp, cnt, wl, obase);
            else       run_half<4, false>(fp, cnt, wl, obase);
            break;
        default:
            if (first) run_half<5, true >(fp, cnt, wl, obase);
            else       run_half<5, false>(fp, cnt, wl, obase);
            break;
    }
}

extern "C" void kernel_launch(void* const* d_in, const int* in_sizes, int n_in,
                              void* d_out, int out_size)
{
    const float4* fmap = (const float4*)d_in[0];   // [1,128,128,256] f32
    const float4* rois = (const float4*)d_in[1];   // [R,4] f32
    float4* out = (float4*)d_out;

    const int R = in_sizes[1] / 4;

    dim3 grid(R, OUT_H);
    dim3 block(C_VEC, 2);
    roi_pool_kernel<<<grid, block>>>(fmap, rois, out);
}